// round 2
// baseline (speedup 1.0000x reference)
#include <cuda_runtime.h>
#include <math.h>

// Problem constants
#define BB   2
#define SS   1024
#define HH   1024
#define NHH  16
#define HDD  64
#define HH2  512
#define SPc  0.05f
#define EPSc 1e-5f

// ---------------- scratch (device globals: no allocation allowed) ----------------
__device__ float g_Q[BB*NHH*SS*HDD];          // [b][h][s][d]
__device__ float g_K[BB*NHH*SS*HDD];
__device__ float g_V[BB*NHH*SS*HDD];
__device__ float g_P[(size_t)BB*NHH*SS*SS];   // scores/probs  [b][h][q][k]  (128 MB)
__device__ float g_ctx[BB*SS*HH];             // [b][s][h]
__device__ float g_specin[BB*HH];
__device__ float g_h1part[BB][4][HH2];
__device__ float g_h1[BB][HH2];
__device__ float g_specpart[BB][8];
__device__ float g_spec[BB];
__device__ float g_msbh[NHH];

// ---------------- small kernels ----------------

// msb_h[h] = mean over 64x64 of msb[h]
__global__ void k_msb(const float* __restrict__ msb) {
    int h = blockIdx.x;
    int tid = threadIdx.x;
    float s = 0.f;
    for (int i = tid; i < HDD*HDD; i += 256) s += msb[h*HDD*HDD + i];
    #pragma unroll
    for (int o = 16; o; o >>= 1) s += __shfl_xor_sync(0xffffffffu, s, o);
    __shared__ float r[8];
    if ((tid & 31) == 0) r[tid >> 5] = s;
    __syncthreads();
    if (tid == 0) {
        float t = 0.f;
        #pragma unroll
        for (int i = 0; i < 8; i++) t += r[i];
        g_msbh[h] = t * (1.f / (HDD*HDD));
    }
}

// spec_in[b][h] = mean over s of query[b][s][h]
__global__ void k_colmean(const float* __restrict__ q) {
    int b = blockIdx.y;
    int c0 = blockIdx.x * 32;
    int tid = threadIdx.x;
    int lane = tid & 31, rg = tid >> 5;            // 8 row-groups x 32 cols
    const float* p = q + (size_t)b*SS*HH + c0 + lane;
    float s = 0.f;
    int r0 = rg * 128;
    #pragma unroll 4
    for (int r = r0; r < r0 + 128; r++) s += p[(size_t)r*HH];
    __shared__ float red[8][33];
    red[rg][lane] = s;
    __syncthreads();
    if (rg == 0) {
        float t = 0.f;
        #pragma unroll
        for (int i = 0; i < 8; i++) t += red[i][lane];
        g_specin[b*HH + c0 + lane] = t * (1.f / SS);
    }
}

// first MLP layer, partial over k-slices of 256
__global__ void k_mlp1(const float* __restrict__ Ws1) {
    int b = blockIdx.y, slice = blockIdx.x;         // 4 slices
    int tid = threadIdx.x;                          // 512 threads
    __shared__ float sin_[256];
    if (tid < 256) sin_[tid] = g_specin[b*HH + slice*256 + tid];
    __syncthreads();
    float acc = 0.f;
    const float* W = Ws1 + (size_t)(slice*256)*HH2 + tid;
    #pragma unroll 4
    for (int k = 0; k < 256; k++) acc += sin_[k] * W[(size_t)k*HH2];
    g_h1part[b][slice][tid] = acc;
}

__global__ void k_mlp1b(const float* __restrict__ bs1) {
    int b = blockIdx.x;
    int tid = threadIdx.x;                          // 512
    float a = bs1[tid] + g_h1part[b][0][tid] + g_h1part[b][1][tid]
                        + g_h1part[b][2][tid] + g_h1part[b][3][tid];
    g_h1[b][tid] = fmaxf(a, 0.f);
}

// second MLP layer + sigmoid + partial mean
__global__ void k_mlp2(const float* __restrict__ Ws2, const float* __restrict__ bs2) {
    int b = blockIdx.y, slice = blockIdx.x;         // 8 slices of 128 outputs
    int tid = threadIdx.x;                          // 128
    __shared__ float h1s[HH2];
    for (int i = tid; i < HH2; i += 128) h1s[i] = g_h1[b][i];
    __syncthreads();
    int n = slice*128 + tid;
    float a = bs2[n];
    const float* W = Ws2 + n;
    #pragma unroll 4
    for (int k = 0; k < HH2; k++) a += h1s[k] * W[(size_t)k*HH];
    float sg = 1.f / (1.f + __expf(-a));
    #pragma unroll
    for (int o = 16; o; o >>= 1) sg += __shfl_xor_sync(0xffffffffu, sg, o);
    __shared__ float r[4];
    if ((tid & 31) == 0) r[tid >> 5] = sg;
    __syncthreads();
    if (tid == 0) g_specpart[b][slice] = r[0] + r[1] + r[2] + r[3];
}

__global__ void k_mlp2b() {
    int b = threadIdx.x;
    if (b < BB) {
        float t = 0.f;
        #pragma unroll
        for (int i = 0; i < 8; i++) t += g_specpart[b][i];
        g_spec[b] = t * (1.f / HH);
    }
}

// ---------------- GEMM kernels (64x64 tile, 4x4/thread, BK=16) ----------------

// QKV projections: C = X@W + b, output in [b][head][s][d] layout
__global__ void __launch_bounds__(256)
k_proj3(const float* __restrict__ Xq, const float* __restrict__ Xk, const float* __restrict__ Xv,
        const float* __restrict__ Wq, const float* __restrict__ bq,
        const float* __restrict__ Wk, const float* __restrict__ bk,
        const float* __restrict__ Wv, const float* __restrict__ bv) {
    const float* X; const float* W; const float* bias; float* Out;
    if (blockIdx.z == 0)      { X = Xq; W = Wq; bias = bq; Out = g_Q; }
    else if (blockIdx.z == 1) { X = Xk; W = Wk; bias = bk; Out = g_K; }
    else                      { X = Xv; W = Wv; bias = bv; Out = g_V; }

    __shared__ float As[16][64];
    __shared__ float Bs[16][64];
    int tid = threadIdx.x;
    int tx = tid & 15, ty = tid >> 4;
    int m0 = blockIdx.y * 64, n0 = blockIdx.x * 64;
    float c[4][4] = {};
    int lm = tid >> 2, lk4 = (tid & 3) << 2;
    int lbk = tid >> 4, lbn4 = (tid & 15) << 2;

    for (int k0 = 0; k0 < HH; k0 += 16) {
        float4 av = *(const float4*)(X + (size_t)(m0 + lm)*HH + k0 + lk4);
        As[lk4  ][lm] = av.x; As[lk4+1][lm] = av.y;
        As[lk4+2][lm] = av.z; As[lk4+3][lm] = av.w;
        *(float4*)(&Bs[lbk][lbn4]) = *(const float4*)(W + (size_t)(k0 + lbk)*HH + n0 + lbn4);
        __syncthreads();
        #pragma unroll
        for (int kk = 0; kk < 16; kk++) {
            float a[4], bb[4];
            #pragma unroll
            for (int i = 0; i < 4; i++) a[i] = As[kk][ty*4 + i];
            #pragma unroll
            for (int j = 0; j < 4; j++) bb[j] = Bs[kk][tx*4 + j];
            #pragma unroll
            for (int i = 0; i < 4; i++)
                #pragma unroll
                for (int j = 0; j < 4; j++) c[i][j] += a[i] * bb[j];
        }
        __syncthreads();
    }
    int nh = n0 >> 6;   // whole 64-wide tile lies in one head
    float bx[4];
    #pragma unroll
    for (int j = 0; j < 4; j++) bx[j] = bias[n0 + tx*4 + j];
    #pragma unroll
    for (int i = 0; i < 4; i++) {
        int m = m0 + ty*4 + i;
        int b = m >> 10, s = m & 1023;
        float4 o;
        o.x = c[i][0] + bx[0]; o.y = c[i][1] + bx[1];
        o.z = c[i][2] + bx[2]; o.w = c[i][3] + bx[3];
        *(float4*)(Out + ((size_t)(b*NHH + nh)*SS + s)*HDD + tx*4) = o;
    }
}

// scores = (Q Kᵀ)/8, then MSB sigmoid gate and spec scale, into g_P
__global__ void __launch_bounds__(256) k_scores() {
    __shared__ float As[16][64];
    __shared__ float Bs[16][64];
    int z = blockIdx.z;                       // b*NH + h
    const float* Q  = g_Q + (size_t)z*SS*HDD;
    const float* Kp = g_K + (size_t)z*SS*HDD;
    float* Pp = g_P + (size_t)z*SS*SS;
    int tid = threadIdx.x;
    int tx = tid & 15, ty = tid >> 4;
    int m0 = blockIdx.y * 64, n0 = blockIdx.x * 64;
    float c[4][4] = {};
    int lm = tid >> 2, lk4 = (tid & 3) << 2;

    for (int k0 = 0; k0 < HDD; k0 += 16) {
        float4 av = *(const float4*)(Q  + (size_t)(m0 + lm)*HDD + k0 + lk4);
        As[lk4  ][lm] = av.x; As[lk4+1][lm] = av.y;
        As[lk4+2][lm] = av.z; As[lk4+3][lm] = av.w;
        float4 bv = *(const float4*)(Kp + (size_t)(n0 + lm)*HDD + k0 + lk4);
        Bs[lk4  ][lm] = bv.x; Bs[lk4+1][lm] = bv.y;
        Bs[lk4+2][lm] = bv.z; Bs[lk4+3][lm] = bv.w;
        __syncthreads();
        #pragma unroll
        for (int kk = 0; kk < 16; kk++) {
            float a[4], bb[4];
            #pragma unroll
            for (int i = 0; i < 4; i++) a[i] = As[kk][ty*4 + i];
            #pragma unroll
            for (int j = 0; j < 4; j++) bb[j] = Bs[kk][tx*4 + j];
            #pragma unroll
            for (int i = 0; i < 4; i++)
                #pragma unroll
                for (int j = 0; j < 4; j++) c[i][j] += a[i] * bb[j];
        }
        __syncthreads();
    }
    float msbh = g_msbh[z & (NHH - 1)];
    float spec = g_spec[z >> 4];
    #pragma unroll
    for (int i = 0; i < 4; i++) {
        int q = m0 + ty*4 + i;
        float4 o;
        float* oo = (float*)&o;
        #pragma unroll
        for (int j = 0; j < 4; j++) {
            float x = c[i][j] * 0.125f;                 // 1/sqrt(64)
            float e = 1.f / (1.f + __expf(-x * msbh)); // sigmoid gate
            oo[j] = x * (1.f + SPc * e) * spec;
        }
        *(float4*)(Pp + (size_t)q*SS + n0 + tx*4) = o;
    }
}

// row softmax over g_P (rows of length 1024)
__global__ void __launch_bounds__(128) k_softmax() {
    size_t row = blockIdx.x;
    float* p = g_P + row * SS;
    int tid = threadIdx.x;
    float v[8];
    float mx = -1e30f;
    #pragma unroll
    for (int i = 0; i < 8; i++) { v[i] = p[tid + i*128]; mx = fmaxf(mx, v[i]); }
    #pragma unroll
    for (int o = 16; o; o >>= 1) mx = fmaxf(mx, __shfl_xor_sync(0xffffffffu, mx, o));
    __shared__ float rm[4], rs[4];
    if ((tid & 31) == 0) rm[tid >> 5] = mx;
    __syncthreads();
    mx = fmaxf(fmaxf(rm[0], rm[1]), fmaxf(rm[2], rm[3]));
    float sum = 0.f;
    #pragma unroll
    for (int i = 0; i < 8; i++) { v[i] = __expf(v[i] - mx); sum += v[i]; }
    #pragma unroll
    for (int o = 16; o; o >>= 1) sum += __shfl_xor_sync(0xffffffffu, sum, o);
    if ((tid & 31) == 0) rs[tid >> 5] = sum;
    __syncthreads();
    sum = rs[0] + rs[1] + rs[2] + rs[3];
    float inv = 1.f / sum;
    #pragma unroll
    for (int i = 0; i < 8; i++) p[tid + i*128] = v[i] * inv;
}

// ctx = P @ V, written to [b][s][h] layout
__global__ void __launch_bounds__(256) k_ctx() {
    __shared__ float As[16][64];
    __shared__ float Bs[16][64];
    int z = blockIdx.y;                        // b*NH + h
    const float* P = g_P + (size_t)z*SS*SS;
    const float* V = g_V + (size_t)z*SS*HDD;
    int tid = threadIdx.x;
    int tx = tid & 15, ty = tid >> 4;
    int m0 = blockIdx.x * 64;
    float c[4][4] = {};
    int lm = tid >> 2, lk4 = (tid & 3) << 2;
    int lbk = tid >> 4, lbn4 = (tid & 15) << 2;

    for (int k0 = 0; k0 < SS; k0 += 16) {
        float4 av = *(const float4*)(P + (size_t)(m0 + lm)*SS + k0 + lk4);
        As[lk4  ][lm] = av.x; As[lk4+1][lm] = av.y;
        As[lk4+2][lm] = av.z; As[lk4+3][lm] = av.w;
        *(float4*)(&Bs[lbk][lbn4]) = *(const float4*)(V + (size_t)(k0 + lbk)*HDD + lbn4);
        __syncthreads();
        #pragma unroll
        for (int kk = 0; kk < 16; kk++) {
            float a[4], bb[4];
            #pragma unroll
            for (int i = 0; i < 4; i++) a[i] = As[kk][ty*4 + i];
            #pragma unroll
            for (int j = 0; j < 4; j++) bb[j] = Bs[kk][tx*4 + j];
            #pragma unroll
            for (int i = 0; i < 4; i++)
                #pragma unroll
                for (int j = 0; j < 4; j++) c[i][j] += a[i] * bb[j];
        }
        __syncthreads();
    }
    int b = z >> 4, h = z & 15;
    #pragma unroll
    for (int i = 0; i < 4; i++) {
        int q = m0 + ty*4 + i;
        float4 o;
        o.x = c[i][0]; o.y = c[i][1]; o.z = c[i][2]; o.w = c[i][3];
        *(float4*)(g_ctx + (size_t)(b*SS + q)*HH + h*HDD + tx*4) = o;
    }
}

// out = ctx @ Wo + bo + query  (pre-LayerNorm), into d_out
__global__ void __launch_bounds__(256)
k_out(const float* __restrict__ Wo, const float* __restrict__ bo,
      const float* __restrict__ query, float* __restrict__ out) {
    __shared__ float As[16][64];
    __shared__ float Bs[16][64];
    int tid = threadIdx.x;
    int tx = tid & 15, ty = tid >> 4;
    int m0 = blockIdx.y * 64, n0 = blockIdx.x * 64;
    float c[4][4] = {};
    int lm = tid >> 2, lk4 = (tid & 3) << 2;
    int lbk = tid >> 4, lbn4 = (tid & 15) << 2;

    for (int k0 = 0; k0 < HH; k0 += 16) {
        float4 av = *(const float4*)(g_ctx + (size_t)(m0 + lm)*HH + k0 + lk4);
        As[lk4  ][lm] = av.x; As[lk4+1][lm] = av.y;
        As[lk4+2][lm] = av.z; As[lk4+3][lm] = av.w;
        *(float4*)(&Bs[lbk][lbn4]) = *(const float4*)(Wo + (size_t)(k0 + lbk)*HH + n0 + lbn4);
        __syncthreads();
        #pragma unroll
        for (int kk = 0; kk < 16; kk++) {
            float a[4], bb[4];
            #pragma unroll
            for (int i = 0; i < 4; i++) a[i] = As[kk][ty*4 + i];
            #pragma unroll
            for (int j = 0; j < 4; j++) bb[j] = Bs[kk][tx*4 + j];
            #pragma unroll
            for (int i = 0; i < 4; i++)
                #pragma unroll
                for (int j = 0; j < 4; j++) c[i][j] += a[i] * bb[j];
        }
        __syncthreads();
    }
    float bx[4];
    #pragma unroll
    for (int j = 0; j < 4; j++) bx[j] = bo[n0 + tx*4 + j];
    #pragma unroll
    for (int i = 0; i < 4; i++) {
        int m = m0 + ty*4 + i;
        float4 qv = *(const float4*)(query + (size_t)m*HH + n0 + tx*4);
        float4 o;
        o.x = c[i][0] + bx[0] + qv.x;
        o.y = c[i][1] + bx[1] + qv.y;
        o.z = c[i][2] + bx[2] + qv.z;
        o.w = c[i][3] + bx[3] + qv.w;
        *(float4*)(out + (size_t)m*HH + n0 + tx*4) = o;
    }
}

// in-place LayerNorm over last dim (rows of 1024)
__global__ void __launch_bounds__(256)
k_ln(float* __restrict__ out, const float* __restrict__ g, const float* __restrict__ b) {
    int row = blockIdx.x;
    float* p = out + (size_t)row * HH;
    int tid = threadIdx.x;
    float v[4];
    float s = 0.f;
    #pragma unroll
    for (int i = 0; i < 4; i++) { v[i] = p[tid + i*256]; s += v[i]; }
    __shared__ float r1[8], r2[8];
    #pragma unroll
    for (int o = 16; o; o >>= 1) s += __shfl_xor_sync(0xffffffffu, s, o);
    if ((tid & 31) == 0) r1[tid >> 5] = s;
    __syncthreads();
    s = 0.f;
    #pragma unroll
    for (int i = 0; i < 8; i++) s += r1[i];
    float mu = s * (1.f / HH);
    float ss = 0.f;
    #pragma unroll
    for (int i = 0; i < 4; i++) { float d = v[i] - mu; ss += d * d; }
    #pragma unroll
    for (int o = 16; o; o >>= 1) ss += __shfl_xor_sync(0xffffffffu, ss, o);
    if ((tid & 31) == 0) r2[tid >> 5] = ss;
    __syncthreads();
    ss = 0.f;
    #pragma unroll
    for (int i = 0; i < 8; i++) ss += r2[i];
    float inv = rsqrtf(ss * (1.f / HH) + EPSc);
    #pragma unroll
    for (int i = 0; i < 4; i++) {
        int n = tid + i*256;
        p[n] = (v[i] - mu) * inv * g[n] + b[n];
    }
}

// ---------------- launch ----------------
extern "C" void kernel_launch(void* const* d_in, const int* in_sizes, int n_in,
                              void* d_out, int out_size) {
    const float* query = (const float*)d_in[0];
    const float* key_t = (const float*)d_in[1];
    const float* value = (const float*)d_in[2];
    const float* Wq  = (const float*)d_in[3];  const float* bq  = (const float*)d_in[4];
    const float* Wk  = (const float*)d_in[5];  const float* bk  = (const float*)d_in[6];
    const float* Wv  = (const float*)d_in[7];  const float* bv  = (const float*)d_in[8];
    const float* msb = (const float*)d_in[9];
    const float* Ws1 = (const float*)d_in[10]; const float* bs1 = (const float*)d_in[11];
    const float* Ws2 = (const float*)d_in[12]; const float* bs2 = (const float*)d_in[13];
    const float* Wo  = (const float*)d_in[14]; const float* bo  = (const float*)d_in[15];
    const float* lng = (const float*)d_in[16]; const float* lnb = (const float*)d_in[17];
    float* out = (float*)d_out;

    // side-path scalars
    k_msb<<<NHH, 256>>>(msb);
    k_colmean<<<dim3(32, BB), 256>>>(query);
    k_mlp1<<<dim3(4, BB), 512>>>(Ws1);
    k_mlp1b<<<BB, 512>>>(bs1);
    k_mlp2<<<dim3(8, BB), 128>>>(Ws2, bs2);
    k_mlp2b<<<1, 32>>>();

    // main path
    k_proj3<<<dim3(16, 32, 3), 256>>>(query, key_t, value, Wq, bq, Wk, bk, Wv, bv);
    k_scores<<<dim3(16, 16, BB*NHH), 256>>>();
    k_softmax<<<BB*NHH*SS, 128>>>();
    k_ctx<<<dim3(16, BB*NHH), 256>>>();
    k_out<<<dim3(16, 32), 256>>>(Wo, bo, query, out);
    k_ln<<<BB*SS, 256>>>(out, lng, lnb);
}

// round 4
// speedup vs baseline: 1.7869x; 1.7869x over previous
#include <cuda_runtime.h>
#include <math.h>
#include <stdint.h>

// Problem constants
#define BB   2
#define SS   1024
#define HH   1024
#define NHH  16
#define HDD  64
#define HH2  512
#define SPc  0.05f
#define EPSc 1e-5f

// ---------------- scratch (device globals: no allocation allowed) ----------------
__device__ float g_Q[BB*NHH*SS*HDD];          // [b][h][s][d], tf32-rounded
__device__ float g_K[BB*NHH*SS*HDD];
__device__ float g_V[BB*NHH*SS*HDD];
__device__ float g_ctx[BB*SS*HH];             // [b][s][h]
__device__ float g_specin[BB*HH];
__device__ float g_h1part[BB][4][HH2];
__device__ float g_h1[BB][HH2];
__device__ float g_specpart[BB][8];
__device__ float g_spec[BB];
__device__ float g_msbh[NHH];

// ---------------- tf32 mma helpers ----------------
__device__ __forceinline__ uint32_t f2tf(float x) {
    uint32_t u;
    asm("cvt.rna.tf32.f32 %0, %1;" : "=r"(u) : "f"(x));
    return u;
}
__device__ __forceinline__ void mma8(float c[4], const uint32_t a[4], uint32_t b0, uint32_t b1) {
    asm volatile(
        "mma.sync.aligned.m16n8k8.row.col.f32.tf32.tf32.f32 "
        "{%0,%1,%2,%3},{%4,%5,%6,%7},{%8,%9},{%0,%1,%2,%3};\n"
        : "+f"(c[0]), "+f"(c[1]), "+f"(c[2]), "+f"(c[3])
        : "r"(a[0]), "r"(a[1]), "r"(a[2]), "r"(a[3]), "r"(b0), "r"(b1));
}

// ---------------- small kernels (side path) ----------------
__global__ void k_msb(const float* __restrict__ msb) {
    int h = blockIdx.x;
    int tid = threadIdx.x;
    float s = 0.f;
    for (int i = tid; i < HDD*HDD; i += 256) s += msb[h*HDD*HDD + i];
    #pragma unroll
    for (int o = 16; o; o >>= 1) s += __shfl_xor_sync(0xffffffffu, s, o);
    __shared__ float r[8];
    if ((tid & 31) == 0) r[tid >> 5] = s;
    __syncthreads();
    if (tid == 0) {
        float t = 0.f;
        #pragma unroll
        for (int i = 0; i < 8; i++) t += r[i];
        g_msbh[h] = t * (1.f / (HDD*HDD));
    }
}

__global__ void k_colmean(const float* __restrict__ q) {
    int b = blockIdx.y;
    int c0 = blockIdx.x * 32;
    int tid = threadIdx.x;
    int lane = tid & 31, rg = tid >> 5;
    const float* p = q + (size_t)b*SS*HH + c0 + lane;
    float s = 0.f;
    int r0 = rg * 128;
    #pragma unroll 4
    for (int r = r0; r < r0 + 128; r++) s += p[(size_t)r*HH];
    __shared__ float red[8][33];
    red[rg][lane] = s;
    __syncthreads();
    if (rg == 0) {
        float t = 0.f;
        #pragma unroll
        for (int i = 0; i < 8; i++) t += red[i][lane];
        g_specin[b*HH + c0 + lane] = t * (1.f / SS);
    }
}

__global__ void k_mlp1(const float* __restrict__ Ws1) {
    int b = blockIdx.y, slice = blockIdx.x;
    int tid = threadIdx.x;
    __shared__ float sin_[256];
    if (tid < 256) sin_[tid] = g_specin[b*HH + slice*256 + tid];
    __syncthreads();
    float acc = 0.f;
    const float* W = Ws1 + (size_t)(slice*256)*HH2 + tid;
    #pragma unroll 4
    for (int k = 0; k < 256; k++) acc += sin_[k] * W[(size_t)k*HH2];
    g_h1part[b][slice][tid] = acc;
}

__global__ void k_mlp1b(const float* __restrict__ bs1) {
    int b = blockIdx.x;
    int tid = threadIdx.x;
    float a = bs1[tid] + g_h1part[b][0][tid] + g_h1part[b][1][tid]
                        + g_h1part[b][2][tid] + g_h1part[b][3][tid];
    g_h1[b][tid] = fmaxf(a, 0.f);
}

__global__ void k_mlp2(const float* __restrict__ Ws2, const float* __restrict__ bs2) {
    int b = blockIdx.y, slice = blockIdx.x;
    int tid = threadIdx.x;
    __shared__ float h1s[HH2];
    for (int i = tid; i < HH2; i += 128) h1s[i] = g_h1[b][i];
    __syncthreads();
    int n = slice*128 + tid;
    float a = bs2[n];
    const float* W = Ws2 + n;
    #pragma unroll 4
    for (int k = 0; k < HH2; k++) a += h1s[k] * W[(size_t)k*HH];
    float sg = 1.f / (1.f + __expf(-a));
    #pragma unroll
    for (int o = 16; o; o >>= 1) sg += __shfl_xor_sync(0xffffffffu, sg, o);
    __shared__ float r[4];
    if ((tid & 31) == 0) r[tid >> 5] = sg;
    __syncthreads();
    if (tid == 0) g_specpart[b][slice] = r[0] + r[1] + r[2] + r[3];
}

__global__ void k_mlp2b() {
    int b = threadIdx.x;
    if (b < BB) {
        float t = 0.f;
        #pragma unroll
        for (int i = 0; i < 8; i++) t += g_specpart[b][i];
        g_spec[b] = t * (1.f / HH);
    }
}

// ---------------- tf32 GEMM: C = X@W (+bias [+resid]) ----------------
// BM=128, BN=64, BK=16, 4 warps (2x2), warp tile 64x32, double-buffered smem.
// mode 0/1/2: out = g_Q/g_K/g_V in [b,h,s,d] layout, values tf32-rounded.
// mode 3:     X = g_ctx, out = out_ext fp32 + bias + resid.
__device__ __forceinline__ void gemm_ldg(const float* X, const float* W, int m0, int n0, int k0,
                                         int arow, int brow, int bcol,
                                         uint32_t ra[4][4], uint32_t rb[2][4]) {
    #pragma unroll
    for (int i = 0; i < 4; i++) {
        float4 v = *(const float4*)(X + (size_t)(m0 + arow)*HH + k0 + i*4);
        ra[i][0] = f2tf(v.x); ra[i][1] = f2tf(v.y); ra[i][2] = f2tf(v.z); ra[i][3] = f2tf(v.w);
    }
    #pragma unroll
    for (int i = 0; i < 2; i++) {
        float4 v = *(const float4*)(W + (size_t)(k0 + brow)*HH + n0 + bcol + i*4);
        rb[i][0] = f2tf(v.x); rb[i][1] = f2tf(v.y); rb[i][2] = f2tf(v.z); rb[i][3] = f2tf(v.w);
    }
}

__global__ void __launch_bounds__(128)
k_gemm(const float* __restrict__ X_ext, const float* __restrict__ W,
       const float* __restrict__ bias, const float* __restrict__ resid,
       float* __restrict__ out_ext, int mode)
{
    __shared__ uint32_t As[2][128][20];   // [buf][m][k], rowstride 20 -> conflict-free frags
    __shared__ uint32_t Bs[2][16][72];    // [buf][k][n], rowstride 72 -> conflict-free frags

    const float* X = (mode == 3) ? g_ctx : X_ext;
    float* Out = (mode == 0) ? g_Q : (mode == 1) ? g_K : (mode == 2) ? g_V : out_ext;

    const int tid = threadIdx.x, lane = tid & 31, wid = tid >> 5;
    const int gr = lane >> 2, gc = lane & 3;
    const int m0 = blockIdx.y * 128, n0 = blockIdx.x * 64;
    const int wm = (wid >> 1) * 64, wn = (wid & 1) * 32;

    const int arow = tid;
    const int brow = tid >> 3, bcol = (tid & 7) * 8;

    float c[4][4][4] = {};
    uint32_t ra[4][4], rb[2][4];

    gemm_ldg(X, W, m0, n0, 0, arow, brow, bcol, ra, rb);
    #pragma unroll
    for (int i = 0; i < 4; i++) *(uint4*)&As[0][arow][i*4] = make_uint4(ra[i][0], ra[i][1], ra[i][2], ra[i][3]);
    #pragma unroll
    for (int i = 0; i < 2; i++) *(uint4*)&Bs[0][brow][bcol + i*4] = make_uint4(rb[i][0], rb[i][1], rb[i][2], rb[i][3]);

    for (int it = 0; it < 64; it++) {
        int cur = it & 1;
        __syncthreads();
        if (it < 63) gemm_ldg(X, W, m0, n0, (it+1)*16, arow, brow, bcol, ra, rb);

        #pragma unroll
        for (int kk = 0; kk < 2; kk++) {
            uint32_t af[4][4], bf[4][2];
            int kq = kk*8 + gc;
            #pragma unroll
            for (int mt = 0; mt < 4; mt++) {
                int r = wm + mt*16 + gr;
                af[mt][0] = As[cur][r][kq];     af[mt][1] = As[cur][r+8][kq];
                af[mt][2] = As[cur][r][kq+4];   af[mt][3] = As[cur][r+8][kq+4];
            }
            #pragma unroll
            for (int nt = 0; nt < 4; nt++) {
                int n = wn + nt*8 + gr;
                bf[nt][0] = Bs[cur][kq][n];  bf[nt][1] = Bs[cur][kq+4][n];
            }
            #pragma unroll
            for (int mt = 0; mt < 4; mt++)
                #pragma unroll
                for (int nt = 0; nt < 4; nt++)
                    mma8(c[mt][nt], af[mt], bf[nt][0], bf[nt][1]);
        }

        if (it < 63) {
            int nb = cur ^ 1;
            #pragma unroll
            for (int i = 0; i < 4; i++) *(uint4*)&As[nb][arow][i*4] = make_uint4(ra[i][0], ra[i][1], ra[i][2], ra[i][3]);
            #pragma unroll
            for (int i = 0; i < 2; i++) *(uint4*)&Bs[nb][brow][bcol + i*4] = make_uint4(rb[i][0], rb[i][1], rb[i][2], rb[i][3]);
        }
    }

    // epilogue
    #pragma unroll
    for (int mt = 0; mt < 4; mt++) {
        #pragma unroll
        for (int f2 = 0; f2 < 2; f2++) {
            int row = m0 + wm + mt*16 + gr + f2*8;
            #pragma unroll
            for (int nt = 0; nt < 4; nt++) {
                int col = n0 + wn + nt*8 + 2*gc;
                float v0 = c[mt][nt][f2*2 + 0] + bias[col];
                float v1 = c[mt][nt][f2*2 + 1] + bias[col + 1];
                if (mode != 3) {
                    int b = row >> 10, s = row & 1023;
                    int head = col >> 6, d = col & 63;
                    float2 o = make_float2(__uint_as_float(f2tf(v0)), __uint_as_float(f2tf(v1)));
                    *(float2*)(Out + (((size_t)(b*NHH + head)*SS + s)*HDD + d)) = o;
                } else {
                    size_t idx = (size_t)row*HH + col;
                    float2 rv = *(const float2*)(resid + idx);
                    *(float2*)(Out + idx) = make_float2(v0 + rv.x, v1 + rv.y);
                }
            }
        }
    }
}

// ---------------- fused flash attention (QK^T -> gate -> online softmax -> PV) ----------------
// Block: (z = b*16+h, q-tile of 128). 8 warps, each owns 16 q-rows.
// K-loop over 32-key tiles. Q kept in registers as mma A-fragments.
__global__ void __launch_bounds__(256)
k_attn()
{
    __shared__ float Ps[128][36];   // P tile (also Q staging), stride 36: conflict-free frags
    __shared__ float Ks[32][68];    // K tile [s][d], stride 68
    __shared__ float Vs[32][72];    // V tile [s][d], stride 72

    const int tid = threadIdx.x, lane = tid & 31, wid = tid >> 5;
    const int gr = lane >> 2, gc = lane & 3;
    const int z = blockIdx.y, q0 = blockIdx.x * 128;
    const float* Qp = g_Q + (size_t)z*SS*HDD;
    const float* Kp = g_K + (size_t)z*SS*HDD;
    const float* Vp = g_V + (size_t)z*SS*HDD;
    const float msbh = g_msbh[z & (NHH - 1)];
    const float spec = g_spec[z >> 4];

    // ---- stage Q (128x64, already tf32-rounded) into registers as A-fragments ----
    uint32_t aq[8][4];
    {
        int row = tid >> 1, cb = (tid & 1) * 16;
        #pragma unroll
        for (int half = 0; half < 2; half++) {
            #pragma unroll
            for (int i = 0; i < 4; i++)
                *(float4*)&Ps[row][cb + i*4] =
                    *(const float4*)(Qp + (size_t)(q0 + row)*HDD + half*32 + cb + i*4);
            __syncthreads();
            int R = wid*16 + gr;
            #pragma unroll
            for (int kf = 0; kf < 4; kf++) {
                int kq = kf*8 + gc;
                aq[half*4 + kf][0] = __float_as_uint(Ps[R][kq]);
                aq[half*4 + kf][1] = __float_as_uint(Ps[R+8][kq]);
                aq[half*4 + kf][2] = __float_as_uint(Ps[R][kq+4]);
                aq[half*4 + kf][3] = __float_as_uint(Ps[R+8][kq+4]);
            }
            __syncthreads();
        }
    }

    float o[8][4] = {};
    float mr[2] = {-INFINITY, -INFINITY};
    float lr[2] = {0.f, 0.f};

    const int rowk = tid >> 3, colk = (tid & 7) * 8;
    float4 pk0 = *(const float4*)(Kp + (size_t)rowk*HDD + colk);
    float4 pk1 = *(const float4*)(Kp + (size_t)rowk*HDD + colk + 4);
    float4 pv0 = *(const float4*)(Vp + (size_t)rowk*HDD + colk);
    float4 pv1 = *(const float4*)(Vp + (size_t)rowk*HDD + colk + 4);

    for (int j = 0; j < 32; j++) {
        __syncthreads();   // prior-iter smem reads complete
        *(float4*)&Ks[rowk][colk]     = pk0;
        *(float4*)&Ks[rowk][colk + 4] = pk1;
        *(float4*)&Vs[rowk][colk]     = pv0;
        *(float4*)&Vs[rowk][colk + 4] = pv1;
        __syncthreads();
        if (j < 31) {
            const float* kb = Kp + (size_t)((j+1)*32 + rowk)*HDD + colk;
            const float* vb = Vp + (size_t)((j+1)*32 + rowk)*HDD + colk;
            pk0 = *(const float4*)kb; pk1 = *(const float4*)(kb + 4);
            pv0 = *(const float4*)vb; pv1 = *(const float4*)(vb + 4);
        }

        // ---- S = Q K^T  (M=16/warp, N=32, K=64) ----
        float s[4][4] = {};
        #pragma unroll
        for (int kf = 0; kf < 8; kf++) {
            int kq = kf*8 + gc;
            #pragma unroll
            for (int nt = 0; nt < 4; nt++) {
                int n = nt*8 + gr;
                uint32_t b0 = __float_as_uint(Ks[n][kq]);
                uint32_t b1 = __float_as_uint(Ks[n][kq + 4]);
                mma8(s[nt], aq[kf], b0, b1);
            }
        }

        // ---- gate + online softmax ----
        float tmax[2] = {-INFINITY, -INFINITY};
        #pragma unroll
        for (int nt = 0; nt < 4; nt++)
            #pragma unroll
            for (int f = 0; f < 4; f++) {
                float x = s[nt][f] * 0.125f;
                float e = __fdividef(1.f, 1.f + __expf(-x * msbh));
                float v = x * (1.f + SPc * e) * spec;
                s[nt][f] = v;
                tmax[f >> 1] = fmaxf(tmax[f >> 1], v);
            }
        #pragma unroll
        for (int h = 0; h < 2; h++) {
            tmax[h] = fmaxf(tmax[h], __shfl_xor_sync(0xffffffffu, tmax[h], 1));
            tmax[h] = fmaxf(tmax[h], __shfl_xor_sync(0xffffffffu, tmax[h], 2));
        }
        float alpha[2];
        #pragma unroll
        for (int h = 0; h < 2; h++) {
            float mnew = fmaxf(mr[h], tmax[h]);
            alpha[h] = __expf(mr[h] - mnew);
            mr[h] = mnew;
            lr[h] *= alpha[h];
        }
        #pragma unroll
        for (int nt = 0; nt < 4; nt++)
            #pragma unroll
            for (int f = 0; f < 4; f++) {
                float p = __expf(s[nt][f] - mr[f >> 1]);
                lr[f >> 1] += p;
                s[nt][f] = p;
            }

        int R = wid*16 + gr;
        __syncwarp();
        #pragma unroll
        for (int nt = 0; nt < 4; nt++) {
            int cc = nt*8 + 2*gc;
            Ps[R][cc]     = __uint_as_float(f2tf(s[nt][0]));
            Ps[R][cc+1]   = __uint_as_float(f2tf(s[nt][1]));
            Ps[R+8][cc]   = __uint_as_float(f2tf(s[nt][2]));
            Ps[R+8][cc+1] = __uint_as_float(f2tf(s[nt][3]));
        }
        __syncwarp();

        #pragma unroll
        for (int nt = 0; nt < 8; nt++) {
            o[nt][0] *= alpha[0]; o[nt][1] *= alpha[0];
            o[nt][2] *= alpha[1]; o[nt][3] *= alpha[1];
        }

        // ---- O += P V  (M=16/warp, N=64, K=32) ----
        #pragma unroll
        for (int kk = 0; kk < 4; kk++) {
            int kq = kk*8 + gc;
            uint32_t ap[4];
            ap[0] = __float_as_uint(Ps[R][kq]);
            ap[1] = __float_as_uint(Ps[R+8][kq]);
            ap[2] = __float_as_uint(Ps[R][kq+4]);
            ap[3] = __float_as_uint(Ps[R+8][kq+4]);
            #pragma unroll
            for (int nt = 0; nt < 8; nt++) {
                int n = nt*8 + gr;
                uint32_t b0 = __float_as_uint(Vs[kq][n]);
                uint32_t b1 = __float_as_uint(Vs[kq+4][n]);
                mma8(o[nt], ap, b0, b1);
            }
        }
    }

    // ---- epilogue: normalize and write ctx ----
    #pragma unroll
    for (int h = 0; h < 2; h++) {
        lr[h] += __shfl_xor_sync(0xffffffffu, lr[h], 1);
        lr[h] += __shfl_xor_sync(0xffffffffu, lr[h], 2);
    }
    float inv0 = __fdividef(1.f, lr[0]);
    float inv1 = __fdividef(1.f, lr[1]);
    int b = z >> 4, hh = z & (NHH - 1);
    int R0 = q0 + wid*16 + gr;
    #pragma unroll
    for (int nt = 0; nt < 8; nt++) {
        int d = hh*HDD + nt*8 + 2*gc;
        *(float2*)(g_ctx + ((size_t)(b*SS + R0)*HH + d))   = make_float2(o[nt][0]*inv0, o[nt][1]*inv0);
        *(float2*)(g_ctx + ((size_t)(b*SS + R0+8)*HH + d)) = make_float2(o[nt][2]*inv1, o[nt][3]*inv1);
    }
}

// ---------------- LayerNorm (rows of 1024, in-place on d_out) ----------------
__global__ void __launch_bounds__(256)
k_ln(float* __restrict__ out, const float* __restrict__ g, const float* __restrict__ b) {
    int row = blockIdx.x;
    float* p = out + (size_t)row * HH;
    int tid = threadIdx.x;
    float v[4];
    float s = 0.f;
    #pragma unroll
    for (int i = 0; i < 4; i++) { v[i] = p[tid + i*256]; s += v[i]; }
    __shared__ float r1[8], r2[8];
    #pragma unroll
    for (int o = 16; o; o >>= 1) s += __shfl_xor_sync(0xffffffffu, s, o);
    if ((tid & 31) == 0) r1[tid >> 5] = s;
    __syncthreads();
    s = 0.f;
    #pragma unroll
    for (int i = 0; i < 8; i++) s += r1[i];
    float mu = s * (1.f / HH);
    float ss = 0.f;
    #pragma unroll
    for (int i = 0; i < 4; i++) { float d = v[i] - mu; ss += d * d; }
    #pragma unroll
    for (int o = 16; o; o >>= 1) ss += __shfl_xor_sync(0xffffffffu, ss, o);
    if ((tid & 31) == 0) r2[tid >> 5] = ss;
    __syncthreads();
    ss = 0.f;
    #pragma unroll
    for (int i = 0; i < 8; i++) ss += r2[i];
    float inv = rsqrtf(ss * (1.f / HH) + EPSc);
    #pragma unroll
    for (int i = 0; i < 4; i++) {
        int n = tid + i*256;
        p[n] = (v[i] - mu) * inv * g[n] + b[n];
    }
}

// ---------------- launch ----------------
extern "C" void kernel_launch(void* const* d_in, const int* in_sizes, int n_in,
                              void* d_out, int out_size) {
    const float* query = (const float*)d_in[0];
    const float* key_t = (const float*)d_in[1];
    const float* value = (const float*)d_in[2];
    const float* Wq  = (const float*)d_in[3];  const float* bq  = (const float*)d_in[4];
    const float* Wk  = (const float*)d_in[5];  const float* bk  = (const float*)d_in[6];
    const float* Wv  = (const float*)d_in[7];  const float* bv  = (const float*)d_in[8];
    const float* msb = (const float*)d_in[9];
    const float* Ws1 = (const float*)d_in[10]; const float* bs1 = (const float*)d_in[11];
    const float* Ws2 = (const float*)d_in[12]; const float* bs2 = (const float*)d_in[13];
    const float* Wo  = (const float*)d_in[14]; const float* bo  = (const float*)d_in[15];
    const float* lng = (const float*)d_in[16]; const float* lnb = (const float*)d_in[17];
    float* out = (float*)d_out;

    // side-path scalars
    k_msb<<<NHH, 256>>>(msb);
    k_colmean<<<dim3(32, BB), 256>>>(query);
    k_mlp1<<<dim3(4, BB), 512>>>(Ws1);
    k_mlp1b<<<BB, 512>>>(bs1);
    k_mlp2<<<dim3(8, BB), 128>>>(Ws2, bs2);
    k_mlp2b<<<1, 32>>>();

    // main path: tf32 tensor-core GEMMs + fused flash attention
    dim3 ggrid(16, 16);
    k_gemm<<<ggrid, 128>>>(query, Wq, bq, nullptr, nullptr, 0);
    k_gemm<<<ggrid, 128>>>(key_t, Wk, bk, nullptr, nullptr, 1);
    k_gemm<<<ggrid, 128>>>(value, Wv, bv, nullptr, nullptr, 2);
    k_attn<<<dim3(8, 32), 256>>>();
    k_gemm<<<ggrid, 128>>>(nullptr, Wo, bo, query, out, 3);
    k_ln<<<BB*SS, 256>>>(out, lng, lnb);
}

// round 6
// speedup vs baseline: 2.6448x; 1.4801x over previous
#include <cuda_runtime.h>
#include <math.h>
#include <stdint.h>

// Problem constants
#define BB   2
#define SS   1024
#define HH   1024
#define NHH  16
#define HDD  64
#define HH2  512
#define SPc  0.05f
#define EPSc 1e-5f

// ---------------- scratch (device globals: no allocation allowed) ----------------
__device__ float g_Q[BB*NHH*SS*HDD];          // [b][h][s][d]
__device__ float g_K[BB*NHH*SS*HDD];
__device__ float g_V[BB*NHH*SS*HDD];
__device__ float g_ctx[BB*SS*HH];             // [b][s][h]
__device__ float g_specin[BB*HH];
__device__ float g_h1part[BB][4][HH2];
__device__ float g_h1[BB][HH2];
__device__ float g_specpart[BB][8];
__device__ float g_spec[BB];
__device__ float g_msbh[NHH];

// ---------------- helpers ----------------
__device__ __forceinline__ void mma8(float c[4], const uint32_t a[4], uint32_t b0, uint32_t b1) {
    asm volatile(
        "mma.sync.aligned.m16n8k8.row.col.f32.tf32.tf32.f32 "
        "{%0,%1,%2,%3},{%4,%5,%6,%7},{%8,%9},{%0,%1,%2,%3};\n"
        : "+f"(c[0]), "+f"(c[1]), "+f"(c[2]), "+f"(c[3])
        : "r"(a[0]), "r"(a[1]), "r"(a[2]), "r"(a[3]), "r"(b0), "r"(b1));
}
__device__ __forceinline__ uint32_t smem_u32(const void* p) {
    return (uint32_t)__cvta_generic_to_shared(p);
}
__device__ __forceinline__ void cp16(uint32_t dst, const void* src) {
    asm volatile("cp.async.cg.shared.global [%0], [%1], 16;" :: "r"(dst), "l"(src));
}
#define CP_COMMIT() asm volatile("cp.async.commit_group;")
#define CP_WAIT1()  asm volatile("cp.async.wait_group 1;")

// ---------------- small kernels (side path) ----------------
__global__ void k_msb(const float* __restrict__ msb) {
    int h = blockIdx.x;
    int tid = threadIdx.x;
    float s = 0.f;
    for (int i = tid; i < HDD*HDD; i += 256) s += msb[h*HDD*HDD + i];
    #pragma unroll
    for (int o = 16; o; o >>= 1) s += __shfl_xor_sync(0xffffffffu, s, o);
    __shared__ float r[8];
    if ((tid & 31) == 0) r[tid >> 5] = s;
    __syncthreads();
    if (tid == 0) {
        float t = 0.f;
        #pragma unroll
        for (int i = 0; i < 8; i++) t += r[i];
        g_msbh[h] = t * (1.f / (HDD*HDD));
    }
}

__global__ void k_colmean(const float* __restrict__ q) {
    int b = blockIdx.y;
    int c0 = blockIdx.x * 32;
    int tid = threadIdx.x;
    int lane = tid & 31, rg = tid >> 5;
    const float* p = q + (size_t)b*SS*HH + c0 + lane;
    float s = 0.f;
    int r0 = rg * 128;
    #pragma unroll 4
    for (int r = r0; r < r0 + 128; r++) s += p[(size_t)r*HH];
    __shared__ float red[8][33];
    red[rg][lane] = s;
    __syncthreads();
    if (rg == 0) {
        float t = 0.f;
        #pragma unroll
        for (int i = 0; i < 8; i++) t += red[i][lane];
        g_specin[b*HH + c0 + lane] = t * (1.f / SS);
    }
}

__global__ void k_mlp1(const float* __restrict__ Ws1) {
    int b = blockIdx.y, slice = blockIdx.x;
    int tid = threadIdx.x;
    __shared__ float sin_[256];
    if (tid < 256) sin_[tid] = g_specin[b*HH + slice*256 + tid];
    __syncthreads();
    float acc = 0.f;
    const float* W = Ws1 + (size_t)(slice*256)*HH2 + tid;
    #pragma unroll 4
    for (int k = 0; k < 256; k++) acc += sin_[k] * W[(size_t)k*HH2];
    g_h1part[b][slice][tid] = acc;
}

__global__ void k_mlp1b(const float* __restrict__ bs1) {
    int b = blockIdx.x;
    int tid = threadIdx.x;
    float a = bs1[tid] + g_h1part[b][0][tid] + g_h1part[b][1][tid]
                        + g_h1part[b][2][tid] + g_h1part[b][3][tid];
    g_h1[b][tid] = fmaxf(a, 0.f);
}

__global__ void k_mlp2(const float* __restrict__ Ws2, const float* __restrict__ bs2) {
    int b = blockIdx.y, slice = blockIdx.x;
    int tid = threadIdx.x;
    __shared__ float h1s[HH2];
    for (int i = tid; i < HH2; i += 128) h1s[i] = g_h1[b][i];
    __syncthreads();
    int n = slice*128 + tid;
    float a = bs2[n];
    const float* W = Ws2 + n;
    #pragma unroll 4
    for (int k = 0; k < HH2; k++) a += h1s[k] * W[(size_t)k*HH];
    float sg = 1.f / (1.f + __expf(-a));
    #pragma unroll
    for (int o = 16; o; o >>= 1) sg += __shfl_xor_sync(0xffffffffu, sg, o);
    __shared__ float r[4];
    if ((tid & 31) == 0) r[tid >> 5] = sg;
    __syncthreads();
    if (tid == 0) g_specpart[b][slice] = r[0] + r[1] + r[2] + r[3];
}

__global__ void k_mlp2b() {
    int b = threadIdx.x;
    if (b < BB) {
        float t = 0.f;
        #pragma unroll
        for (int i = 0; i < 8; i++) t += g_specpart[b][i];
        g_spec[b] = t * (1.f / HH);
    }
}

// ---------------- tf32 GEMM, cp.async double-buffered ----------------
// BM=128, BN=128, BK=16, 256 threads (8 warps 2x4), warp tile 64x32.
// Raw fp32 fed to tf32 HMMA (HW truncates mantissa).
// MODE 0: QKV projections (blockIdx.z picks q/k/v), out to g_Q/K/V in [b,h,s,d].
// MODE 1: out = g_ctx@Wo + bias + resid -> out_ext.
template<int MODE>
__global__ void __launch_bounds__(256)
k_gemm(const float* __restrict__ Xq, const float* __restrict__ Xk, const float* __restrict__ Xv,
       const float* __restrict__ Wq, const float* __restrict__ bq,
       const float* __restrict__ Wk, const float* __restrict__ bk,
       const float* __restrict__ Wv, const float* __restrict__ bv,
       const float* __restrict__ resid, float* __restrict__ out_ext)
{
    __shared__ float As[2][128][20];     // [buf][m][k] stride 20: conflict-free frags
    __shared__ float Bs[2][16][136];     // [buf][k][n] stride 136: conflict-free frags

    const float* X; const float* W; const float* bias; float* Out;
    if (MODE == 0) {
        int zz = blockIdx.z;
        X    = (zz == 0) ? Xq : (zz == 1) ? Xk : Xv;
        W    = (zz == 0) ? Wq : (zz == 1) ? Wk : Wv;
        bias = (zz == 0) ? bq : (zz == 1) ? bk : bv;
        Out  = (zz == 0) ? g_Q : (zz == 1) ? g_K : g_V;
    } else {
        X = g_ctx; W = Wq; bias = bq; Out = out_ext;
    }

    const int tid = threadIdx.x, lane = tid & 31, wid = tid >> 5;
    const int gr = lane >> 2, gc = lane & 3;
    const int m0 = blockIdx.y * 128, n0 = blockIdx.x * 128;
    const int wm = (wid & 1) * 64, wn = (wid >> 1) * 32;

    // cp.async chunk maps (16B = 4 floats)
    const int a_row0 = tid >> 2,  a_kc = (tid & 3) << 2;     // +64 rows for i=1
    const int b_row0 = tid >> 5,  b_nc = (tid & 31) << 2;    // +8 rows for i=1

    float c[4][4][4] = {};

    // prefetch k0=0 into buf 0
    {
        cp16(smem_u32(&As[0][a_row0     ][a_kc]), X + (size_t)(m0 + a_row0     )*HH + a_kc);
        cp16(smem_u32(&As[0][a_row0 + 64][a_kc]), X + (size_t)(m0 + a_row0 + 64)*HH + a_kc);
        cp16(smem_u32(&Bs[0][b_row0     ][b_nc]), W + (size_t)(b_row0    )*HH + n0 + b_nc);
        cp16(smem_u32(&Bs[0][b_row0 + 8 ][b_nc]), W + (size_t)(b_row0 + 8)*HH + n0 + b_nc);
        CP_COMMIT();
    }

    for (int it = 0; it < 64; it++) {
        const int cur = it & 1;
        if (it < 63) {
            const int k0 = (it + 1) * 16, nb = cur ^ 1;
            cp16(smem_u32(&As[nb][a_row0     ][a_kc]), X + (size_t)(m0 + a_row0     )*HH + k0 + a_kc);
            cp16(smem_u32(&As[nb][a_row0 + 64][a_kc]), X + (size_t)(m0 + a_row0 + 64)*HH + k0 + a_kc);
            cp16(smem_u32(&Bs[nb][b_row0     ][b_nc]), W + (size_t)(k0 + b_row0    )*HH + n0 + b_nc);
            cp16(smem_u32(&Bs[nb][b_row0 + 8 ][b_nc]), W + (size_t)(k0 + b_row0 + 8)*HH + n0 + b_nc);
        }
        CP_COMMIT();
        CP_WAIT1();
        __syncthreads();

        #pragma unroll
        for (int kk = 0; kk < 2; kk++) {
            const int kq = kk*8 + gc;
            uint32_t af[4][4], bf[4][2];
            #pragma unroll
            for (int mt = 0; mt < 4; mt++) {
                int r = wm + mt*16 + gr;
                af[mt][0] = __float_as_uint(As[cur][r  ][kq  ]);
                af[mt][1] = __float_as_uint(As[cur][r+8][kq  ]);
                af[mt][2] = __float_as_uint(As[cur][r  ][kq+4]);
                af[mt][3] = __float_as_uint(As[cur][r+8][kq+4]);
            }
            #pragma unroll
            for (int nt = 0; nt < 4; nt++) {
                int n = wn + nt*8 + gr;
                bf[nt][0] = __float_as_uint(Bs[cur][kq  ][n]);
                bf[nt][1] = __float_as_uint(Bs[cur][kq+4][n]);
            }
            #pragma unroll
            for (int mt = 0; mt < 4; mt++)
                #pragma unroll
                for (int nt = 0; nt < 4; nt++)
                    mma8(c[mt][nt], af[mt], bf[nt][0], bf[nt][1]);
        }
        __syncthreads();
    }

    // epilogue
    #pragma unroll
    for (int mt = 0; mt < 4; mt++) {
        #pragma unroll
        for (int f2 = 0; f2 < 2; f2++) {
            int row = m0 + wm + mt*16 + gr + f2*8;
            #pragma unroll
            for (int nt = 0; nt < 4; nt++) {
                int col = n0 + wn + nt*8 + 2*gc;
                float v0 = c[mt][nt][f2*2 + 0] + bias[col];
                float v1 = c[mt][nt][f2*2 + 1] + bias[col + 1];
                if (MODE == 0) {
                    int b = row >> 10, s = row & 1023;
                    int head = col >> 6, d = col & 63;
                    *(float2*)(Out + (((size_t)(b*NHH + head)*SS + s)*HDD + d)) = make_float2(v0, v1);
                } else {
                    size_t idx = (size_t)row*HH + col;
                    float2 rv = *(const float2*)(resid + idx);
                    *(float2*)(Out + idx) = make_float2(v0 + rv.x, v1 + rv.y);
                }
            }
        }
    }
}

// ---------------- fused flash attention (QK^T -> gate -> online softmax -> PV) ----------------
__global__ void __launch_bounds__(256)
k_attn()
{
    __shared__ float Ps[128][36];   // P tile (also Q staging), stride 36
    __shared__ float Ks[32][68];    // K tile [s][d], stride 68
    __shared__ float Vs[32][72];    // V tile [s][d], stride 72

    const int tid = threadIdx.x, lane = tid & 31, wid = tid >> 5;
    const int gr = lane >> 2, gc = lane & 3;
    const int z = blockIdx.y, q0 = blockIdx.x * 128;
    const float* Qp = g_Q + (size_t)z*SS*HDD;
    const float* Kp = g_K + (size_t)z*SS*HDD;
    const float* Vp = g_V + (size_t)z*SS*HDD;
    const float msbh = g_msbh[z & (NHH - 1)];
    const float spec = g_spec[z >> 4];

    // ---- stage Q (128x64) into registers as A-fragments ----
    uint32_t aq[8][4];
    {
        int row = tid >> 1, cb = (tid & 1) * 16;
        #pragma unroll
        for (int half = 0; half < 2; half++) {
            #pragma unroll
            for (int i = 0; i < 4; i++)
                *(float4*)&Ps[row][cb + i*4] =
                    *(const float4*)(Qp + (size_t)(q0 + row)*HDD + half*32 + cb + i*4);
            __syncthreads();
            int R = wid*16 + gr;
            #pragma unroll
            for (int kf = 0; kf < 4; kf++) {
                int kq = kf*8 + gc;
                aq[half*4 + kf][0] = __float_as_uint(Ps[R][kq]);
                aq[half*4 + kf][1] = __float_as_uint(Ps[R+8][kq]);
                aq[half*4 + kf][2] = __float_as_uint(Ps[R][kq+4]);
                aq[half*4 + kf][3] = __float_as_uint(Ps[R+8][kq+4]);
            }
            __syncthreads();
        }
    }

    float o[8][4] = {};
    float mr[2] = {-INFINITY, -INFINITY};
    float lr[2] = {0.f, 0.f};

    const int rowk = tid >> 3, colk = (tid & 7) * 8;
    float4 pk0 = *(const float4*)(Kp + (size_t)rowk*HDD + colk);
    float4 pk1 = *(const float4*)(Kp + (size_t)rowk*HDD + colk + 4);
    float4 pv0 = *(const float4*)(Vp + (size_t)rowk*HDD + colk);
    float4 pv1 = *(const float4*)(Vp + (size_t)rowk*HDD + colk + 4);

    for (int j = 0; j < 32; j++) {
        __syncthreads();
        *(float4*)&Ks[rowk][colk]     = pk0;
        *(float4*)&Ks[rowk][colk + 4] = pk1;
        *(float4*)&Vs[rowk][colk]     = pv0;
        *(float4*)&Vs[rowk][colk + 4] = pv1;
        __syncthreads();
        if (j < 31) {
            const float* kb = Kp + (size_t)((j+1)*32 + rowk)*HDD + colk;
            const float* vb = Vp + (size_t)((j+1)*32 + rowk)*HDD + colk;
            pk0 = *(const float4*)kb; pk1 = *(const float4*)(kb + 4);
            pv0 = *(const float4*)vb; pv1 = *(const float4*)(vb + 4);
        }

        // ---- S = Q K^T ----
        float s[4][4] = {};
        #pragma unroll
        for (int kf = 0; kf < 8; kf++) {
            int kq = kf*8 + gc;
            #pragma unroll
            for (int nt = 0; nt < 4; nt++) {
                int n = nt*8 + gr;
                uint32_t b0 = __float_as_uint(Ks[n][kq]);
                uint32_t b1 = __float_as_uint(Ks[n][kq + 4]);
                mma8(s[nt], aq[kf], b0, b1);
            }
        }

        // ---- gate + online softmax ----
        float tmax[2] = {-INFINITY, -INFINITY};
        #pragma unroll
        for (int nt = 0; nt < 4; nt++)
            #pragma unroll
            for (int f = 0; f < 4; f++) {
                float x = s[nt][f] * 0.125f;
                float e = __fdividef(1.f, 1.f + __expf(-x * msbh));
                float v = x * (1.f + SPc * e) * spec;
                s[nt][f] = v;
                tmax[f >> 1] = fmaxf(tmax[f >> 1], v);
            }
        #pragma unroll
        for (int h = 0; h < 2; h++) {
            tmax[h] = fmaxf(tmax[h], __shfl_xor_sync(0xffffffffu, tmax[h], 1));
            tmax[h] = fmaxf(tmax[h], __shfl_xor_sync(0xffffffffu, tmax[h], 2));
        }
        float alpha[2];
        #pragma unroll
        for (int h = 0; h < 2; h++) {
            float mnew = fmaxf(mr[h], tmax[h]);
            alpha[h] = __expf(mr[h] - mnew);
            mr[h] = mnew;
            lr[h] *= alpha[h];
        }
        #pragma unroll
        for (int nt = 0; nt < 4; nt++)
            #pragma unroll
            for (int f = 0; f < 4; f++) {
                float p = __expf(s[nt][f] - mr[f >> 1]);
                lr[f >> 1] += p;
                s[nt][f] = p;
            }

        int R = wid*16 + gr;
        __syncwarp();
        #pragma unroll
        for (int nt = 0; nt < 4; nt++) {
            int cc = nt*8 + 2*gc;
            Ps[R][cc]     = s[nt][0];
            Ps[R][cc+1]   = s[nt][1];
            Ps[R+8][cc]   = s[nt][2];
            Ps[R+8][cc+1] = s[nt][3];
        }
        __syncwarp();

        #pragma unroll
        for (int nt = 0; nt < 8; nt++) {
            o[nt][0] *= alpha[0]; o[nt][1] *= alpha[0];
            o[nt][2] *= alpha[1]; o[nt][3] *= alpha[1];
        }

        // ---- O += P V ----
        #pragma unroll
        for (int kk = 0; kk < 4; kk++) {
            int kq = kk*8 + gc;
            uint32_t ap[4];
            ap[0] = __float_as_uint(Ps[R][kq]);
            ap[1] = __float_as_uint(Ps[R+8][kq]);
            ap[2] = __float_as_uint(Ps[R][kq+4]);
            ap[3] = __float_as_uint(Ps[R+8][kq+4]);
            #pragma unroll
            for (int nt = 0; nt < 8; nt++) {
                int n = nt*8 + gr;
                uint32_t b0 = __float_as_uint(Vs[kq][n]);
                uint32_t b1 = __float_as_uint(Vs[kq+4][n]);
                mma8(o[nt], ap, b0, b1);
            }
        }
    }

    // ---- epilogue ----
    #pragma unroll
    for (int h = 0; h < 2; h++) {
        lr[h] += __shfl_xor_sync(0xffffffffu, lr[h], 1);
        lr[h] += __shfl_xor_sync(0xffffffffu, lr[h], 2);
    }
    float inv0 = __fdividef(1.f, lr[0]);
    float inv1 = __fdividef(1.f, lr[1]);
    int b = z >> 4, hh = z & (NHH - 1);
    int R0 = q0 + wid*16 + gr;
    #pragma unroll
    for (int nt = 0; nt < 8; nt++) {
        int d = hh*HDD + nt*8 + 2*gc;
        *(float2*)(g_ctx + ((size_t)(b*SS + R0)*HH + d))   = make_float2(o[nt][0]*inv0, o[nt][1]*inv0);
        *(float2*)(g_ctx + ((size_t)(b*SS + R0+8)*HH + d)) = make_float2(o[nt][2]*inv1, o[nt][3]*inv1);
    }
}

// ---------------- LayerNorm ----------------
__global__ void __launch_bounds__(256)
k_ln(float* __restrict__ out, const float* __restrict__ g, const float* __restrict__ b) {
    int row = blockIdx.x;
    float* p = out + (size_t)row * HH;
    int tid = threadIdx.x;
    float v[4];
    float s = 0.f;
    #pragma unroll
    for (int i = 0; i < 4; i++) { v[i] = p[tid + i*256]; s += v[i]; }
    __shared__ float r1[8], r2[8];
    #pragma unroll
    for (int o = 16; o; o >>= 1) s += __shfl_xor_sync(0xffffffffu, s, o);
    if ((tid & 31) == 0) r1[tid >> 5] = s;
    __syncthreads();
    s = 0.f;
    #pragma unroll
    for (int i = 0; i < 8; i++) s += r1[i];
    float mu = s * (1.f / HH);
    float ss = 0.f;
    #pragma unroll
    for (int i = 0; i < 4; i++) { float d = v[i] - mu; ss += d * d; }
    #pragma unroll
    for (int o = 16; o; o >>= 1) ss += __shfl_xor_sync(0xffffffffu, ss, o);
    if ((tid & 31) == 0) r2[tid >> 5] = ss;
    __syncthreads();
    ss = 0.f;
    #pragma unroll
    for (int i = 0; i < 8; i++) ss += r2[i];
    float inv = rsqrtf(ss * (1.f / HH) + EPSc);
    #pragma unroll
    for (int i = 0; i < 4; i++) {
        int n = tid + i*256;
        p[n] = (v[i] - mu) * inv * g[n] + b[n];
    }
}

// ---------------- launch ----------------
extern "C" void kernel_launch(void* const* d_in, const int* in_sizes, int n_in,
                              void* d_out, int out_size) {
    const float* query = (const float*)d_in[0];
    const float* key_t = (const float*)d_in[1];
    const float* value = (const float*)d_in[2];
    const float* Wq  = (const float*)d_in[3];  const float* bq  = (const float*)d_in[4];
    const float* Wk  = (const float*)d_in[5];  const float* bk  = (const float*)d_in[6];
    const float* Wv  = (const float*)d_in[7];  const float* bv  = (const float*)d_in[8];
    const float* msb = (const float*)d_in[9];
    const float* Ws1 = (const float*)d_in[10]; const float* bs1 = (const float*)d_in[11];
    const float* Ws2 = (const float*)d_in[12]; const float* bs2 = (const float*)d_in[13];
    const float* Wo  = (const float*)d_in[14]; const float* bo  = (const float*)d_in[15];
    const float* lng = (const float*)d_in[16]; const float* lnb = (const float*)d_in[17];
    float* out = (float*)d_out;

    // side-path scalars
    k_msb<<<NHH, 256>>>(msb);
    k_colmean<<<dim3(32, BB), 256>>>(query);
    k_mlp1<<<dim3(4, BB), 512>>>(Ws1);
    k_mlp1b<<<BB, 512>>>(bs1);
    k_mlp2<<<dim3(8, BB), 128>>>(Ws2, bs2);
    k_mlp2b<<<1, 32>>>();

    // main path
    k_gemm<0><<<dim3(8, 16, 3), 256>>>(query, key_t, value, Wq, bq, Wk, bk, Wv, bv, nullptr, nullptr);
    k_attn<<<dim3(8, 32), 256>>>();
    k_gemm<1><<<dim3(8, 16), 256>>>(nullptr, nullptr, nullptr, Wo, bo, nullptr, nullptr, nullptr, nullptr, query, out);
    k_ln<<<BB*SS, 256>>>(out, lng, lnb);
}